// round 12
// baseline (speedup 1.0000x reference)
#include <cuda_runtime.h>
#include <cuda_bf16.h>
#include <cstdint>

constexpr int NB = 8, C = 64, HW = 4096;
constexpr int QT = 128;                // q rows per CTA (32 per warp, 2 mtiles)
constexpr int KT = 64;                 // keys per iteration tile
constexpr int NKT = HW / KT;           // 64
constexpr int NSPLIT = 2;              // key splits per q-tile
constexpr int ITERS = NKT / NSPLIT;    // 32 key tiles per CTA
constexpr float EPS_BN = 1e-5f;
constexpr float QSCALE = 0.125f * 1.4426950408889634f;  // (1/sqrt(64)) * log2(e)

__device__ __align__(256) float g_scale[C];
__device__ __align__(256) float g_shift[C];
__device__ __align__(256) float g_ps[512];
__device__ __align__(256) float g_pq[512];
__device__ __align__(256) __nv_bfloat16 g_Q[(size_t)NB * HW * C];   // [n,i,c] pre-scaled
__device__ __align__(256) __nv_bfloat16 g_Kb[(size_t)NB * HW * C];  // [n,j,c]
__device__ __align__(256) __nv_bfloat16 g_V[(size_t)NB * HW * C];   // [n,j,c]
__device__ __align__(256) float g_Op[(size_t)NSPLIT * NB * HW * C]; // unnormalized O partials
__device__ __align__(256) float g_Ls[(size_t)NSPLIT * NB * HW];     // row exp-sums

// ---------- helpers ----------
__device__ __forceinline__ uint32_t smem_u32(const void* p) {
    uint32_t a;
    asm("{ .reg .u64 t; cvta.to.shared.u64 t, %1; cvt.u32.u64 %0, t; }" : "=r"(a) : "l"(p));
    return a;
}
__device__ __forceinline__ float ex2f(float x) {
    float y; asm("ex2.approx.ftz.f32 %0, %1;" : "=f"(y) : "f"(x)); return y;
}
__device__ __forceinline__ void cp_async16(uint32_t s, const void* g) {
    asm volatile("cp.async.cg.shared.global [%0], [%1], 16;" :: "r"(s), "l"(g));
}
__device__ __forceinline__ void cp_commit() { asm volatile("cp.async.commit_group;"); }

__device__ __forceinline__ void mma16816(float* d, const uint32_t* a, uint32_t b0, uint32_t b1) {
    asm volatile(
        "mma.sync.aligned.m16n8k16.row.col.f32.bf16.bf16.f32 "
        "{%0,%1,%2,%3}, {%4,%5,%6,%7}, {%8,%9}, {%0,%1,%2,%3};"
        : "+f"(d[0]), "+f"(d[1]), "+f"(d[2]), "+f"(d[3])
        : "r"(a[0]), "r"(a[1]), "r"(a[2]), "r"(a[3]), "r"(b0), "r"(b1));
}
__device__ __forceinline__ void ldsm4(uint32_t* r, uint32_t addr) {
    asm volatile("ldmatrix.sync.aligned.m8n8.x4.shared.b16 {%0,%1,%2,%3}, [%4];"
        : "=r"(r[0]), "=r"(r[1]), "=r"(r[2]), "=r"(r[3]) : "r"(addr));
}
__device__ __forceinline__ void ldsm4t(uint32_t* r, uint32_t addr) {
    asm volatile("ldmatrix.sync.aligned.m8n8.x4.trans.shared.b16 {%0,%1,%2,%3}, [%4];"
        : "=r"(r[0]), "=r"(r[1]), "=r"(r[2]), "=r"(r[3]) : "r"(addr));
}
__device__ __forceinline__ uint32_t packbf(float a, float b) {
    __nv_bfloat162 t = __floats2bfloat162_rn(a, b);
    return *reinterpret_cast<uint32_t*>(&t);
}

// ---------- kernel 1a: BN partial sums ----------
__global__ __launch_bounds__(256) void bn_part(const float* __restrict__ x) {
    int c = blockIdx.x >> 3, s = blockIdx.x & 7, t = threadIdx.x;
    const float* p = x + ((size_t)s * C + c) * HW;
    float sm = 0.f, sq = 0.f;
#pragma unroll
    for (int i = 0; i < HW / 256; i++) { float v = p[t + i * 256]; sm += v; sq += v * v; }
    __shared__ float rs[256], rq[256];
    rs[t] = sm; rq[t] = sq; __syncthreads();
    for (int o = 128; o > 0; o >>= 1) {
        if (t < o) { rs[t] += rs[t + o]; rq[t] += rq[t + o]; }
        __syncthreads();
    }
    if (t == 0) { g_ps[c * 8 + s] = rs[0]; g_pq[c * 8 + s] = rq[0]; }
}

// ---------- kernel 1b: BN finalize ----------
__global__ void bn_fin(const float* __restrict__ gamma, const float* __restrict__ beta) {
    int c = threadIdx.x;
    float sm = 0.f, sq = 0.f;
#pragma unroll
    for (int k = 0; k < 8; k++) { sm += g_ps[c * 8 + k]; sq += g_pq[c * 8 + k]; }
    float inv = 1.0f / (float)(NB * HW);
    float mean = sm * inv;
    float var = sq * inv - mean * mean;
    float sc = rsqrtf(var + EPS_BN) * gamma[c];
    g_scale[c] = sc;
    g_shift[c] = beta[c] - mean * sc;
}

// ---------- kernel 2: BN-apply + QKV via HMMA ----------
__global__ __launch_bounds__(128) void qkv_kernel(
    const float* __restrict__ x,
    const float* __restrict__ wq, const float* __restrict__ bq,
    const float* __restrict__ wk, const float* __restrict__ bk,
    const float* __restrict__ wv, const float* __restrict__ bv) {
    __shared__ __align__(16) char sX[128 * 128];
    __shared__ __align__(16) char sW[3][64 * 128];
    int t = threadIdx.x, wid = t >> 5, l = t & 31;
    int n = blockIdx.y;
    int p0 = blockIdx.x * 128;
    uint32_t sXa = smem_u32(sX);

    {
        const float* xb = x + (size_t)n * C * HW + p0 + t;
        int r7 = t & 7;
#pragma unroll
        for (int cp = 0; cp < 32; cp++) {
            int c0 = 2 * cp;
            float v0 = xb[(size_t)c0 * HW] * g_scale[c0] + g_shift[c0];
            float v1 = xb[(size_t)(c0 + 1) * HW] * g_scale[c0 + 1] + g_shift[c0 + 1];
            uint32_t pk = packbf(v0, v1);
            uint32_t off = ((uint32_t)(((c0 >> 3) ^ r7) << 4)) + (uint32_t)((c0 & 7) * 2);
            *reinterpret_cast<uint32_t*>(&((char*)sX)[t * 128 + off]) = pk;
        }
    }
    {
        const float* ws[3] = {wq, wk, wv};
#pragma unroll
        for (int w = 0; w < 3; w++) {
            const float* wp = ws[w];
#pragma unroll
            for (int i = 0; i < 16; i++) {
                int idx = t + i * 128;
                int o = idx >> 5, cp = idx & 31, c0 = 2 * cp;
                float2 wv2 = *reinterpret_cast<const float2*>(wp + o * 64 + c0);
                uint32_t pk = packbf(wv2.x, wv2.y);
                uint32_t off = ((uint32_t)(((c0 >> 3) ^ (o & 7)) << 4)) + (uint32_t)((c0 & 7) * 2);
                *reinterpret_cast<uint32_t*>(&sW[w][o * 128 + off]) = pk;
            }
        }
    }
    __syncthreads();

    uint32_t A[2][4][4];
    {
        int arow = (l & 7) + ((l >> 3) & 1) * 8;
        int l7 = l & 7;
#pragma unroll
        for (int mt2 = 0; mt2 < 2; mt2++) {
            int m0 = (wid * 2 + mt2) * 16;
#pragma unroll
            for (int kt = 0; kt < 4; kt++) {
                uint32_t chunk = (uint32_t)((kt * 2 + (l >> 4)) ^ l7);
                ldsm4(A[mt2][kt], sXa + (uint32_t)(m0 + arow) * 128 + (chunk << 4));
            }
        }
    }

    const float* biases[3] = {bq, bk, bv};
    __nv_bfloat16* outs[3] = {g_Q + (size_t)n * HW * C + (size_t)p0 * C,
                              g_Kb + (size_t)n * HW * C + (size_t)p0 * C,
                              g_V + (size_t)n * HW * C + (size_t)p0 * C};
    float scales[3] = {QSCALE, 1.f, 1.f};

    int brow = l & 7;
    uint32_t bx0 = (uint32_t)(((0 + (l >> 3)) ^ brow) << 4);
    uint32_t bx4 = (uint32_t)(((4 + (l >> 3)) ^ brow) << 4);

#pragma unroll
    for (int w = 0; w < 3; w++) {
        uint32_t sWa = smem_u32(sW[w]);
        float acc[2][8][4];
#pragma unroll
        for (int a = 0; a < 2; a++)
#pragma unroll
            for (int b = 0; b < 8; b++)
#pragma unroll
                for (int cc = 0; cc < 4; cc++) acc[a][b][cc] = 0.f;

#pragma unroll
        for (int nt = 0; nt < 8; nt++) {
            uint32_t base = sWa + (uint32_t)(nt * 8 + brow) * 128;
            uint32_t B[8];
            ldsm4(B, base + bx0);
            ldsm4(B + 4, base + bx4);
#pragma unroll
            for (int mt2 = 0; mt2 < 2; mt2++) {
                mma16816(acc[mt2][nt], A[mt2][0], B[0], B[1]);
                mma16816(acc[mt2][nt], A[mt2][1], B[2], B[3]);
                mma16816(acc[mt2][nt], A[mt2][2], B[4], B[5]);
                mma16816(acc[mt2][nt], A[mt2][3], B[6], B[7]);
            }
        }
        const float* bias = biases[w];
        float s = scales[w];
        __nv_bfloat16* op = outs[w];
#pragma unroll
        for (int nt = 0; nt < 8; nt++) {
            int col = nt * 8 + (l & 3) * 2;
            float2 bb = *reinterpret_cast<const float2*>(bias + col);
#pragma unroll
            for (int mt2 = 0; mt2 < 2; mt2++) {
                int row0 = (wid * 2 + mt2) * 16 + (l >> 2);
                uint32_t pk0 = packbf((acc[mt2][nt][0] + bb.x) * s, (acc[mt2][nt][1] + bb.y) * s);
                uint32_t pk1 = packbf((acc[mt2][nt][2] + bb.x) * s, (acc[mt2][nt][3] + bb.y) * s);
                *reinterpret_cast<uint32_t*>(op + (size_t)row0 * C + col) = pk0;
                *reinterpret_cast<uint32_t*>(op + (size_t)(row0 + 8) * C + col) = pk1;
            }
        }
    }
}

// ---------- kernel 3: flash attention, split-K (2 halves), partial outputs ----------
constexpr int ROWB = 144;
constexpr int TILE_B = KT * ROWB;

__global__ __launch_bounds__(128) void attn_kernel() {
    __shared__ __align__(16) char sK[2][TILE_B];  // [key][ch]
    __shared__ __align__(16) char sV[2][TILE_B];  // [key][ch]
    int t = threadIdx.x, wid = t >> 5, lane = t & 31;
    int n = blockIdx.y;
    int qt = blockIdx.x >> 1, h = blockIdx.x & 1;   // q-tile, key-half
    int qrow0 = qt * QT + wid * 32;                 // warp owns 32 rows = 2 mtiles
    int kt0 = h * ITERS;
    int m = lane >> 2;
    int qp = (lane & 3) * 2;

    const __nv_bfloat16* Kg = g_Kb + (size_t)n * HW * C;
    const __nv_bfloat16* Vg = g_V + (size_t)n * HW * C;

    uint32_t lds_off = (uint32_t)((lane & 7) * ROWB + (lane >> 3) * 16);
    uint32_t ldt_off = (uint32_t)(((lane & 7) + ((lane >> 3) & 1) * 8) * ROWB + (lane >> 4) * 16);
    uint32_t sKa = smem_u32(sK);
    uint32_t sVa = smem_u32(sV);

    uint32_t qa[2][4][4];
#pragma unroll
    for (int mt = 0; mt < 2; mt++) {
        const __nv_bfloat16* Qb = g_Q + ((size_t)n * HW + qrow0 + mt * 16) * C;
#pragma unroll
        for (int kb = 0; kb < 4; kb++) {
            qa[mt][kb][0] = *(const uint32_t*)(Qb + (size_t)m * C + kb * 16 + qp);
            qa[mt][kb][1] = *(const uint32_t*)(Qb + (size_t)(m + 8) * C + kb * 16 + qp);
            qa[mt][kb][2] = *(const uint32_t*)(Qb + (size_t)m * C + kb * 16 + 8 + qp);
            qa[mt][kb][3] = *(const uint32_t*)(Qb + (size_t)(m + 8) * C + kb * 16 + 8 + qp);
        }
    }

    float oacc[2][8][4];
#pragma unroll
    for (int mt = 0; mt < 2; mt++)
#pragma unroll
        for (int i = 0; i < 8; i++)
#pragma unroll
            for (int j = 0; j < 4; j++) oacc[mt][i][j] = 0.f;
    float lsum[2][2] = {{0.f, 0.f}, {0.f, 0.f}};

    auto prefetch = [&](int b, int kt) {
#pragma unroll
        for (int rr = 0; rr < 4; rr++) {
            int ch = t + rr * 128;
            int row = ch >> 3, col = ch & 7;
            cp_async16(sKa + (uint32_t)(b * TILE_B + row * ROWB + col * 16),
                       Kg + ((size_t)(kt * KT + row)) * C + col * 8);
            cp_async16(sVa + (uint32_t)(b * TILE_B + row * ROWB + col * 16),
                       Vg + ((size_t)(kt * KT + row)) * C + col * 8);
        }
        cp_commit();
    };

    prefetch(0, kt0);

    for (int it = 0; it < ITERS; it++) {
        asm volatile("cp.async.wait_group 0;");
        __syncthreads();
        if (it + 1 < ITERS) prefetch((it + 1) & 1, kt0 + it + 1);

        uint32_t kb_a = sKa + (uint32_t)((it & 1) * TILE_B) + lds_off;
        uint32_t vb_a = sVa + (uint32_t)((it & 1) * TILE_B) + ldt_off;

        uint32_t pa[2][4][4];
#pragma unroll
        for (int kc = 0; kc < 4; kc++) {
            float sacc[2][2][4];
#pragma unroll
            for (int j = 0; j < 2; j++) {
                int nt = kc * 2 + j;
                uint32_t B[8];
                ldsm4(B, kb_a + nt * 8 * ROWB);
                ldsm4(B + 4, kb_a + nt * 8 * ROWB + 64);
#pragma unroll
                for (int mt = 0; mt < 2; mt++) {
#pragma unroll
                    for (int z = 0; z < 4; z++) sacc[mt][j][z] = 0.f;
                    mma16816(sacc[mt][j], qa[mt][0], B[0], B[1]);
                    mma16816(sacc[mt][j], qa[mt][1], B[2], B[3]);
                    mma16816(sacc[mt][j], qa[mt][2], B[4], B[5]);
                    mma16816(sacc[mt][j], qa[mt][3], B[6], B[7]);
                }
            }
#pragma unroll
            for (int mt = 0; mt < 2; mt++) {
#pragma unroll
                for (int j = 0; j < 2; j++) {
                    float e0 = ex2f(sacc[mt][j][0]);
                    float e1 = ex2f(sacc[mt][j][1]);
                    float e2 = ex2f(sacc[mt][j][2]);
                    float e3 = ex2f(sacc[mt][j][3]);
                    lsum[mt][0] += e0 + e1;
                    lsum[mt][1] += e2 + e3;
                    pa[mt][kc][j * 2 + 0] = packbf(e0, e1);
                    pa[mt][kc][j * 2 + 1] = packbf(e2, e3);
                }
            }
        }

#pragma unroll
        for (int np = 0; np < 4; np++) {
#pragma unroll
            for (int kc = 0; kc < 4; kc++) {
                uint32_t B[4];
                ldsm4t(B, vb_a + (uint32_t)(kc * 16 * ROWB + np * 32));
#pragma unroll
                for (int mt = 0; mt < 2; mt++) {
                    mma16816(oacc[mt][2 * np], pa[mt][kc], B[0], B[1]);
                    mma16816(oacc[mt][2 * np + 1], pa[mt][kc], B[2], B[3]);
                }
            }
        }
    }

    // store unnormalized partials + row exp-sums
    size_t hb = (size_t)(h * NB + n) * HW;
#pragma unroll
    for (int mt = 0; mt < 2; mt++) {
        float l0 = lsum[mt][0], l1 = lsum[mt][1];
        l0 += __shfl_xor_sync(0xffffffffu, l0, 1);
        l0 += __shfl_xor_sync(0xffffffffu, l0, 2);
        l1 += __shfl_xor_sync(0xffffffffu, l1, 1);
        l1 += __shfl_xor_sync(0xffffffffu, l1, 2);

        int row = qrow0 + mt * 16 + m;
        float* orow0 = g_Op + (hb + row) * C;
        float* orow1 = orow0 + 8 * C;
#pragma unroll
        for (int ct = 0; ct < 8; ct++) {
            int col = ct * 8 + qp;
            *reinterpret_cast<float2*>(orow0 + col) = make_float2(oacc[mt][ct][0], oacc[mt][ct][1]);
            *reinterpret_cast<float2*>(orow1 + col) = make_float2(oacc[mt][ct][2], oacc[mt][ct][3]);
        }
        if ((lane & 3) == 0) {
            g_Ls[hb + row] = l0;
            g_Ls[hb + row + 8] = l1;
        }
    }
}

// ---------- kernel 4: combine halves + output conv + residual ----------
constexpr int OP = 64;
__global__ __launch_bounds__(256) void out_kernel(
    const float* __restrict__ x, const float* __restrict__ wo,
    const float* __restrict__ bo, float* __restrict__ out) {
    __shared__ float sW[C * C];
    __shared__ __align__(16) float sv[C][OP];
    __shared__ float sinv[C];
    int t = threadIdx.x;
    int n = blockIdx.y;
    int p0 = blockIdx.x * OP;
    int g = t >> 6, pl = t & 63, p = p0 + pl;

    float xv[16];
    const float* xb = x + (size_t)n * C * HW + p;
#pragma unroll
    for (int o = 0; o < 16; o++) xv[o] = xb[(size_t)(g * 16 + o) * HW];

    for (int j = t; j < C * C; j += 256) sW[(j & 63) * C + (j >> 6)] = wo[j];
    if (t < C) {
        // raw-reshape: row for view-channel t at block p0 is i = t*64 + p0/64
        int i = t * 64 + (p0 >> 6);
        float l = g_Ls[(size_t)n * HW + i] + g_Ls[(size_t)(NB + n) * HW + i];
        sinv[t] = 1.f / l;
    }
    __syncthreads();

    {
        const float* O0 = g_Op + (size_t)n * HW * C + p0;           // flat [c'][p] view
        const float* O1 = g_Op + (size_t)(NB + n) * HW * C + p0;
        for (int j = t; j < C * 16; j += 256) {
            int c = j >> 4, w = j & 15;
            float iv = sinv[c];
            float4 a = *reinterpret_cast<const float4*>(O0 + (size_t)c * HW + w * 4);
            float4 b = *reinterpret_cast<const float4*>(O1 + (size_t)c * HW + w * 4);
            float4 v;
            v.x = (a.x + b.x) * iv; v.y = (a.y + b.y) * iv;
            v.z = (a.z + b.z) * iv; v.w = (a.w + b.w) * iv;
            *reinterpret_cast<float4*>(&sv[c][w * 4]) = v;
        }
    }
    __syncthreads();

    float acc[16];
#pragma unroll
    for (int o = 0; o < 16; o++) acc[o] = bo[g * 16 + o];
#pragma unroll
    for (int c = 0; c < C; c++) {
        float v = sv[c][pl];
#pragma unroll
        for (int o = 0; o < 16; o++) acc[o] += sW[c * C + g * 16 + o] * v;
    }
    float* ob = out + (size_t)n * C * HW + p;
#pragma unroll
    for (int o = 0; o < 16; o++)
        ob[(size_t)(g * 16 + o) * HW] = acc[o] + xv[o];
}

extern "C" void kernel_launch(void* const* d_in, const int* in_sizes, int n_in,
                              void* d_out, int out_size) {
    const float* x     = (const float*)d_in[0];
    const float* gamma = (const float*)d_in[1];
    const float* beta  = (const float*)d_in[2];
    const float* wq    = (const float*)d_in[3];
    const float* bq    = (const float*)d_in[4];
    const float* wk    = (const float*)d_in[5];
    const float* bk    = (const float*)d_in[6];
    const float* wv    = (const float*)d_in[7];
    const float* bv    = (const float*)d_in[8];
    const float* wo    = (const float*)d_in[9];
    const float* bo    = (const float*)d_in[10];
    float* out = (float*)d_out;

    bn_part<<<512, 256>>>(x);
    bn_fin<<<1, 64>>>(gamma, beta);
    qkv_kernel<<<dim3(HW / 128, NB), 128>>>(x, wq, bq, wk, bk, wv, bv);
    attn_kernel<<<dim3((HW / QT) * NSPLIT, NB), 128>>>();
    out_kernel<<<dim3(HW / OP, NB), 256>>>(x, wo, bo, out);
}

// round 13
// speedup vs baseline: 1.1634x; 1.1634x over previous
#include <cuda_runtime.h>
#include <cuda_bf16.h>
#include <cstdint>

constexpr int NB = 8, C = 64, HW = 4096;
constexpr int QT = 128;                // q rows per CTA (32 per warp, 2 mtiles)
constexpr int KT = 64;                 // keys per iteration
constexpr int NKT = HW / KT;           // 64
constexpr float EPS_BN = 1e-5f;
constexpr float QSCALE = 0.125f * 1.4426950408889634f;  // (1/sqrt(64)) * log2(e)

__device__ __align__(256) float g_scale[C];
__device__ __align__(256) float g_shift[C];
__device__ __align__(256) float g_ps[512];
__device__ __align__(256) float g_pq[512];
__device__ __align__(256) __nv_bfloat16 g_Q[(size_t)NB * HW * C];   // [n,i,c] pre-scaled
__device__ __align__(256) __nv_bfloat16 g_Kb[(size_t)NB * HW * C];  // [n,j,c]
__device__ __align__(256) __nv_bfloat16 g_V[(size_t)NB * HW * C];   // [n,j,c]
__device__ __align__(256) float g_O[(size_t)NB * HW * C];           // [n,i,c]

// ---------- helpers ----------
__device__ __forceinline__ uint32_t smem_u32(const void* p) {
    uint32_t a;
    asm("{ .reg .u64 t; cvta.to.shared.u64 t, %1; cvt.u32.u64 %0, t; }" : "=r"(a) : "l"(p));
    return a;
}
__device__ __forceinline__ float ex2f(float x) {
    float y; asm("ex2.approx.ftz.f32 %0, %1;" : "=f"(y) : "f"(x)); return y;
}
__device__ __forceinline__ void cp_async16(uint32_t s, const void* g) {
    asm volatile("cp.async.cg.shared.global [%0], [%1], 16;" :: "r"(s), "l"(g));
}
__device__ __forceinline__ void cp_commit() { asm volatile("cp.async.commit_group;"); }

__device__ __forceinline__ void mma16816(float* d, const uint32_t* a, uint32_t b0, uint32_t b1) {
    asm volatile(
        "mma.sync.aligned.m16n8k16.row.col.f32.bf16.bf16.f32 "
        "{%0,%1,%2,%3}, {%4,%5,%6,%7}, {%8,%9}, {%0,%1,%2,%3};"
        : "+f"(d[0]), "+f"(d[1]), "+f"(d[2]), "+f"(d[3])
        : "r"(a[0]), "r"(a[1]), "r"(a[2]), "r"(a[3]), "r"(b0), "r"(b1));
}
__device__ __forceinline__ void ldsm4(uint32_t* r, uint32_t addr) {
    asm volatile("ldmatrix.sync.aligned.m8n8.x4.shared.b16 {%0,%1,%2,%3}, [%4];"
        : "=r"(r[0]), "=r"(r[1]), "=r"(r[2]), "=r"(r[3]) : "r"(addr));
}
__device__ __forceinline__ void ldsm4t(uint32_t* r, uint32_t addr) {
    asm volatile("ldmatrix.sync.aligned.m8n8.x4.trans.shared.b16 {%0,%1,%2,%3}, [%4];"
        : "=r"(r[0]), "=r"(r[1]), "=r"(r[2]), "=r"(r[3]) : "r"(addr));
}
__device__ __forceinline__ uint32_t packbf(float a, float b) {
    __nv_bfloat162 t = __floats2bfloat162_rn(a, b);
    return *reinterpret_cast<uint32_t*>(&t);
}

// ---------- kernel 1a: BN partial sums ----------
__global__ __launch_bounds__(256) void bn_part(const float* __restrict__ x) {
    int c = blockIdx.x >> 3, s = blockIdx.x & 7, t = threadIdx.x;
    const float* p = x + ((size_t)s * C + c) * HW;
    float sm = 0.f, sq = 0.f;
#pragma unroll
    for (int i = 0; i < HW / 256; i++) { float v = p[t + i * 256]; sm += v; sq += v * v; }
    __shared__ float rs[256], rq[256];
    rs[t] = sm; rq[t] = sq; __syncthreads();
    for (int o = 128; o > 0; o >>= 1) {
        if (t < o) { rs[t] += rs[t + o]; rq[t] += rq[t + o]; }
        __syncthreads();
    }
    if (t == 0) { g_ps[c * 8 + s] = rs[0]; g_pq[c * 8 + s] = rq[0]; }
}

// ---------- kernel 1b: BN finalize ----------
__global__ void bn_fin(const float* __restrict__ gamma, const float* __restrict__ beta) {
    int c = threadIdx.x;
    float sm = 0.f, sq = 0.f;
#pragma unroll
    for (int k = 0; k < 8; k++) { sm += g_ps[c * 8 + k]; sq += g_pq[c * 8 + k]; }
    float inv = 1.0f / (float)(NB * HW);
    float mean = sm * inv;
    float var = sq * inv - mean * mean;
    float sc = rsqrtf(var + EPS_BN) * gamma[c];
    g_scale[c] = sc;
    g_shift[c] = beta[c] - mean * sc;
}

// ---------- kernel 2: BN-apply + QKV via HMMA ----------
__global__ __launch_bounds__(128) void qkv_kernel(
    const float* __restrict__ x,
    const float* __restrict__ wq, const float* __restrict__ bq,
    const float* __restrict__ wk, const float* __restrict__ bk,
    const float* __restrict__ wv, const float* __restrict__ bv) {
    __shared__ __align__(16) char sX[128 * 128];
    __shared__ __align__(16) char sW[3][64 * 128];
    int t = threadIdx.x, wid = t >> 5, l = t & 31;
    int n = blockIdx.y;
    int p0 = blockIdx.x * 128;
    uint32_t sXa = smem_u32(sX);

    {
        const float* xb = x + (size_t)n * C * HW + p0 + t;
        int r7 = t & 7;
#pragma unroll
        for (int cp = 0; cp < 32; cp++) {
            int c0 = 2 * cp;
            float v0 = xb[(size_t)c0 * HW] * g_scale[c0] + g_shift[c0];
            float v1 = xb[(size_t)(c0 + 1) * HW] * g_scale[c0 + 1] + g_shift[c0 + 1];
            uint32_t pk = packbf(v0, v1);
            uint32_t off = ((uint32_t)(((c0 >> 3) ^ r7) << 4)) + (uint32_t)((c0 & 7) * 2);
            *reinterpret_cast<uint32_t*>(&((char*)sX)[t * 128 + off]) = pk;
        }
    }
    {
        const float* ws[3] = {wq, wk, wv};
#pragma unroll
        for (int w = 0; w < 3; w++) {
            const float* wp = ws[w];
#pragma unroll
            for (int i = 0; i < 16; i++) {
                int idx = t + i * 128;
                int o = idx >> 5, cp = idx & 31, c0 = 2 * cp;
                float2 wv2 = *reinterpret_cast<const float2*>(wp + o * 64 + c0);
                uint32_t pk = packbf(wv2.x, wv2.y);
                uint32_t off = ((uint32_t)(((c0 >> 3) ^ (o & 7)) << 4)) + (uint32_t)((c0 & 7) * 2);
                *reinterpret_cast<uint32_t*>(&sW[w][o * 128 + off]) = pk;
            }
        }
    }
    __syncthreads();

    uint32_t A[2][4][4];
    {
        int arow = (l & 7) + ((l >> 3) & 1) * 8;
        int l7 = l & 7;
#pragma unroll
        for (int mt2 = 0; mt2 < 2; mt2++) {
            int m0 = (wid * 2 + mt2) * 16;
#pragma unroll
            for (int kt = 0; kt < 4; kt++) {
                uint32_t chunk = (uint32_t)((kt * 2 + (l >> 4)) ^ l7);
                ldsm4(A[mt2][kt], sXa + (uint32_t)(m0 + arow) * 128 + (chunk << 4));
            }
        }
    }

    const float* biases[3] = {bq, bk, bv};
    __nv_bfloat16* outs[3] = {g_Q + (size_t)n * HW * C + (size_t)p0 * C,
                              g_Kb + (size_t)n * HW * C + (size_t)p0 * C,
                              g_V + (size_t)n * HW * C + (size_t)p0 * C};
    float scales[3] = {QSCALE, 1.f, 1.f};

    int brow = l & 7;
    uint32_t bx0 = (uint32_t)(((0 + (l >> 3)) ^ brow) << 4);
    uint32_t bx4 = (uint32_t)(((4 + (l >> 3)) ^ brow) << 4);

#pragma unroll
    for (int w = 0; w < 3; w++) {
        uint32_t sWa = smem_u32(sW[w]);
        float acc[2][8][4];
#pragma unroll
        for (int a = 0; a < 2; a++)
#pragma unroll
            for (int b = 0; b < 8; b++)
#pragma unroll
                for (int cc = 0; cc < 4; cc++) acc[a][b][cc] = 0.f;

#pragma unroll
        for (int nt = 0; nt < 8; nt++) {
            uint32_t base = sWa + (uint32_t)(nt * 8 + brow) * 128;
            uint32_t B[8];
            ldsm4(B, base + bx0);
            ldsm4(B + 4, base + bx4);
#pragma unroll
            for (int mt2 = 0; mt2 < 2; mt2++) {
                mma16816(acc[mt2][nt], A[mt2][0], B[0], B[1]);
                mma16816(acc[mt2][nt], A[mt2][1], B[2], B[3]);
                mma16816(acc[mt2][nt], A[mt2][2], B[4], B[5]);
                mma16816(acc[mt2][nt], A[mt2][3], B[6], B[7]);
            }
        }
        const float* bias = biases[w];
        float s = scales[w];
        __nv_bfloat16* op = outs[w];
#pragma unroll
        for (int nt = 0; nt < 8; nt++) {
            int col = nt * 8 + (l & 3) * 2;
            float2 bb = *reinterpret_cast<const float2*>(bias + col);
#pragma unroll
            for (int mt2 = 0; mt2 < 2; mt2++) {
                int row0 = (wid * 2 + mt2) * 16 + (l >> 2);
                uint32_t pk0 = packbf((acc[mt2][nt][0] + bb.x) * s, (acc[mt2][nt][1] + bb.y) * s);
                uint32_t pk1 = packbf((acc[mt2][nt][2] + bb.x) * s, (acc[mt2][nt][3] + bb.y) * s);
                *reinterpret_cast<uint32_t*>(op + (size_t)row0 * C + col) = pk0;
                *reinterpret_cast<uint32_t*>(op + (size_t)(row0 + 8) * C + col) = pk1;
            }
        }
    }
}

// ---------- kernel 3: flash attention (R9 exact — measured 104.3 us) ----------
constexpr int ROWB = 144;

__global__ __launch_bounds__(128) void attn_kernel() {
    __shared__ __align__(16) char sK[2][KT * ROWB];
    __shared__ __align__(16) char sV[2][KT * ROWB];
    int t = threadIdx.x, wid = t >> 5, lane = t & 31;
    int n = blockIdx.y, qt = blockIdx.x;
    int qrow0 = qt * QT + wid * 32;
    int m = lane >> 2;
    int qp = (lane & 3) * 2;

    const __nv_bfloat16* Kg = g_Kb + (size_t)n * HW * C;
    const __nv_bfloat16* Vg = g_V + (size_t)n * HW * C;

    uint32_t lds_off = (uint32_t)((lane & 7) * ROWB + (lane >> 3) * 16);
    uint32_t ldt_off = (uint32_t)(((lane & 7) + ((lane >> 3) & 1) * 8) * ROWB + (lane >> 4) * 16);
    uint32_t sKa = smem_u32(sK);
    uint32_t sVa = smem_u32(sV);

    uint32_t qa[2][4][4];
#pragma unroll
    for (int mt = 0; mt < 2; mt++) {
        const __nv_bfloat16* Qb = g_Q + ((size_t)n * HW + qrow0 + mt * 16) * C;
#pragma unroll
        for (int kb = 0; kb < 4; kb++) {
            qa[mt][kb][0] = *(const uint32_t*)(Qb + (size_t)m * C + kb * 16 + qp);
            qa[mt][kb][1] = *(const uint32_t*)(Qb + (size_t)(m + 8) * C + kb * 16 + qp);
            qa[mt][kb][2] = *(const uint32_t*)(Qb + (size_t)m * C + kb * 16 + 8 + qp);
            qa[mt][kb][3] = *(const uint32_t*)(Qb + (size_t)(m + 8) * C + kb * 16 + 8 + qp);
        }
    }

    float oacc[2][8][4];
#pragma unroll
    for (int mt = 0; mt < 2; mt++)
#pragma unroll
        for (int i = 0; i < 8; i++)
#pragma unroll
            for (int j = 0; j < 4; j++) oacc[mt][i][j] = 0.f;
    float lsum[2][2] = {{0.f, 0.f}, {0.f, 0.f}};

    auto prefetch = [&](int b, int kt) {
#pragma unroll
        for (int rr = 0; rr < 4; rr++) {
            int ch = t + rr * 128;
            int row = ch >> 3, col = ch & 7;
            cp_async16(sKa + (uint32_t)(b * KT * ROWB + row * ROWB + col * 16),
                       Kg + ((size_t)(kt * KT + row)) * C + col * 8);
            cp_async16(sVa + (uint32_t)(b * KT * ROWB + row * ROWB + col * 16),
                       Vg + ((size_t)(kt * KT + row)) * C + col * 8);
        }
        cp_commit();
    };

    prefetch(0, 0);

    for (int kt = 0; kt < NKT; kt++) {
        asm volatile("cp.async.wait_group 0;");
        __syncthreads();
        if (kt + 1 < NKT) prefetch((kt + 1) & 1, kt + 1);

        uint32_t kb_a = sKa + (uint32_t)((kt & 1) * KT * ROWB) + lds_off;
        uint32_t vb_a = sVa + (uint32_t)((kt & 1) * KT * ROWB) + ldt_off;

        uint32_t pa[2][4][4];
#pragma unroll
        for (int kc = 0; kc < 4; kc++) {
            float sacc[2][2][4];
#pragma unroll
            for (int j = 0; j < 2; j++) {
                int nt = kc * 2 + j;
                uint32_t B[8];
                ldsm4(B, kb_a + nt * 8 * ROWB);
                ldsm4(B + 4, kb_a + nt * 8 * ROWB + 64);
#pragma unroll
                for (int mt = 0; mt < 2; mt++) {
#pragma unroll
                    for (int z = 0; z < 4; z++) sacc[mt][j][z] = 0.f;
                    mma16816(sacc[mt][j], qa[mt][0], B[0], B[1]);
                    mma16816(sacc[mt][j], qa[mt][1], B[2], B[3]);
                    mma16816(sacc[mt][j], qa[mt][2], B[4], B[5]);
                    mma16816(sacc[mt][j], qa[mt][3], B[6], B[7]);
                }
            }
#pragma unroll
            for (int mt = 0; mt < 2; mt++) {
#pragma unroll
                for (int j = 0; j < 2; j++) {
                    float e0 = ex2f(sacc[mt][j][0]);
                    float e1 = ex2f(sacc[mt][j][1]);
                    float e2 = ex2f(sacc[mt][j][2]);
                    float e3 = ex2f(sacc[mt][j][3]);
                    lsum[mt][0] += e0 + e1;
                    lsum[mt][1] += e2 + e3;
                    pa[mt][kc][j * 2 + 0] = packbf(e0, e1);
                    pa[mt][kc][j * 2 + 1] = packbf(e2, e3);
                }
            }
        }

#pragma unroll
        for (int np = 0; np < 4; np++) {
#pragma unroll
            for (int kc = 0; kc < 4; kc++) {
                uint32_t B[4];
                ldsm4t(B, vb_a + (uint32_t)(kc * 16 * ROWB + np * 32));
#pragma unroll
                for (int mt = 0; mt < 2; mt++) {
                    mma16816(oacc[mt][2 * np], pa[mt][kc], B[0], B[1]);
                    mma16816(oacc[mt][2 * np + 1], pa[mt][kc], B[2], B[3]);
                }
            }
        }
    }

#pragma unroll
    for (int mt = 0; mt < 2; mt++) {
        float l0 = lsum[mt][0], l1 = lsum[mt][1];
        l0 += __shfl_xor_sync(0xffffffffu, l0, 1);
        l0 += __shfl_xor_sync(0xffffffffu, l0, 2);
        l1 += __shfl_xor_sync(0xffffffffu, l1, 1);
        l1 += __shfl_xor_sync(0xffffffffu, l1, 2);
        float inv0 = 1.f / l0, inv1 = 1.f / l1;

        float* orow0 = g_O + ((size_t)n * HW + qrow0 + mt * 16 + m) * C;
        float* orow1 = orow0 + 8 * C;
#pragma unroll
        for (int ct = 0; ct < 8; ct++) {
            int col = ct * 8 + qp;
            float2 v0 = make_float2(oacc[mt][ct][0] * inv0, oacc[mt][ct][1] * inv0);
            float2 v1 = make_float2(oacc[mt][ct][2] * inv1, oacc[mt][ct][3] * inv1);
            *reinterpret_cast<float2*>(orow0 + col) = v0;
            *reinterpret_cast<float2*>(orow1 + col) = v1;
        }
    }
}

// ---------- kernel 4: output conv via HMMA + residual ----------
// Phase 1: smem[0..16384) = O staged (128 p-rows x 128B bf16 swizzled)
//          smem[16384..24576) = wo (64 o-rows x 128B bf16 swizzled)
// Phase 2 (after barrier): smem[0..16896) = sP [64 o-rows x 264B bf16] (aliases)
__global__ __launch_bounds__(128) void out_kernel(
    const float* __restrict__ x, const float* __restrict__ wo,
    const float* __restrict__ bo, float* __restrict__ out) {
    __shared__ __align__(16) char smem[24576];
    int t = threadIdx.x, wid = t >> 5, l = t & 31;
    int n = blockIdx.y;
    int p0 = blockIdx.x * 128;
    uint32_t sOa = smem_u32(smem);
    uint32_t sWa = sOa + 16384;

    // stage O (raw-reshape flat view [c'][p], stride HW) as bf16, swizzled
    {
        const float* Ob = g_O + (size_t)n * C * HW + p0 + t;
        int r7 = t & 7;
#pragma unroll
        for (int cp = 0; cp < 32; cp++) {
            int c0 = 2 * cp;
            float v0 = Ob[(size_t)c0 * HW];
            float v1 = Ob[(size_t)(c0 + 1) * HW];
            uint32_t pk = packbf(v0, v1);
            uint32_t off = ((uint32_t)(((c0 >> 3) ^ r7) << 4)) + (uint32_t)((c0 & 7) * 2);
            *reinterpret_cast<uint32_t*>(&smem[t * 128 + off]) = pk;
        }
    }
    // stage wo
#pragma unroll
    for (int i = 0; i < 16; i++) {
        int idx = t + i * 128;
        int o = idx >> 5, cp = idx & 31, c0 = 2 * cp;
        float2 wv2 = *reinterpret_cast<const float2*>(wo + o * 64 + c0);
        uint32_t pk = packbf(wv2.x, wv2.y);
        uint32_t off = ((uint32_t)(((c0 >> 3) ^ (o & 7)) << 4)) + (uint32_t)((c0 & 7) * 2);
        *reinterpret_cast<uint32_t*>(&smem[16384 + o * 128 + off]) = pk;
    }
    __syncthreads();

    // A fragments (positions x channels)
    uint32_t A[2][4][4];
    {
        int arow = (l & 7) + ((l >> 3) & 1) * 8;
        int l7 = l & 7;
#pragma unroll
        for (int mt2 = 0; mt2 < 2; mt2++) {
            int m0 = (wid * 2 + mt2) * 16;
#pragma unroll
            for (int kt = 0; kt < 4; kt++) {
                uint32_t chunk = (uint32_t)((kt * 2 + (l >> 4)) ^ l7);
                ldsm4(A[mt2][kt], sOa + (uint32_t)(m0 + arow) * 128 + (chunk << 4));
            }
        }
    }

    int brow = l & 7;
    uint32_t bx0 = (uint32_t)(((0 + (l >> 3)) ^ brow) << 4);
    uint32_t bx4 = (uint32_t)(((4 + (l >> 3)) ^ brow) << 4);

    float acc[2][8][4];
#pragma unroll
    for (int a = 0; a < 2; a++)
#pragma unroll
        for (int b = 0; b < 8; b++)
#pragma unroll
            for (int cc = 0; cc < 4; cc++) acc[a][b][cc] = 0.f;

#pragma unroll
    for (int nt = 0; nt < 8; nt++) {
        uint32_t base = sWa + (uint32_t)(nt * 8 + brow) * 128;
        uint32_t B[8];
        ldsm4(B, base + bx0);
        ldsm4(B + 4, base + bx4);
#pragma unroll
        for (int mt2 = 0; mt2 < 2; mt2++) {
            mma16816(acc[mt2][nt], A[mt2][0], B[0], B[1]);
            mma16816(acc[mt2][nt], A[mt2][1], B[2], B[3]);
            mma16816(acc[mt2][nt], A[mt2][2], B[4], B[5]);
            mma16816(acc[mt2][nt], A[mt2][3], B[6], B[7]);
        }
    }
    __syncthreads();   // all mma reads of sW / A-loads of sO done before sP overwrite

    // write sP[o][p] bf16 (pitch 264B), bias added
    __nv_bfloat16* sP = reinterpret_cast<__nv_bfloat16*>(smem);
#pragma unroll
    for (int nt = 0; nt < 8; nt++) {
        int col = nt * 8 + (l & 3) * 2;
        float2 bb = *reinterpret_cast<const float2*>(bo + col);
#pragma unroll
        for (int mt2 = 0; mt2 < 2; mt2++) {
            int row0 = (wid * 2 + mt2) * 16 + (l >> 2);
            *reinterpret_cast<__nv_bfloat16*>(&smem[col * 264 + row0 * 2])       = __float2bfloat16(acc[mt2][nt][0] + bb.x);
            *reinterpret_cast<__nv_bfloat16*>(&smem[(col + 1) * 264 + row0 * 2]) = __float2bfloat16(acc[mt2][nt][1] + bb.y);
            *reinterpret_cast<__nv_bfloat16*>(&smem[col * 264 + (row0 + 8) * 2])       = __float2bfloat16(acc[mt2][nt][2] + bb.x);
            *reinterpret_cast<__nv_bfloat16*>(&smem[(col + 1) * 264 + (row0 + 8) * 2]) = __float2bfloat16(acc[mt2][nt][3] + bb.y);
        }
    }
    __syncthreads();

    // coalesced residual + store: warp handles 16 output channels
#pragma unroll
    for (int oo = 0; oo < 16; oo++) {
        int o = wid * 16 + oo;
        uint2 pk = *reinterpret_cast<const uint2*>(&smem[o * 264 + l * 8]);
        __nv_bfloat162 b01 = *reinterpret_cast<__nv_bfloat162*>(&pk.x);
        __nv_bfloat162 b23 = *reinterpret_cast<__nv_bfloat162*>(&pk.y);
        const float* xb = x + ((size_t)n * C + o) * HW + p0 + l * 4;
        float4 xv = *reinterpret_cast<const float4*>(xb);
        float4 r;
        r.x = __bfloat162float(b01.x) + xv.x;
        r.y = __bfloat162float(b01.y) + xv.y;
        r.z = __bfloat162float(b23.x) + xv.z;
        r.w = __bfloat162float(b23.y) + xv.w;
        *reinterpret_cast<float4*>(out + ((size_t)n * C + o) * HW + p0 + l * 4) = r;
    }
}

extern "C" void kernel_launch(void* const* d_in, const int* in_sizes, int n_in,
                              void* d_out, int out_size) {
    const float* x     = (const float*)d_in[0];
    const float* gamma = (const float*)d_in[1];
    const float* beta  = (const float*)d_in[2];
    const float* wq    = (const float*)d_in[3];
    const float* bq    = (const float*)d_in[4];
    const float* wk    = (const float*)d_in[5];
    const float* bk    = (const float*)d_in[6];
    const float* wv    = (const float*)d_in[7];
    const float* bv    = (const float*)d_in[8];
    const float* wo    = (const float*)d_in[9];
    const float* bo    = (const float*)d_in[10];
    float* out = (float*)d_out;

    bn_part<<<512, 256>>>(x);
    bn_fin<<<1, 64>>>(gamma, beta);
    qkv_kernel<<<dim3(HW / 128, NB), 128>>>(x, wq, bq, wk, bk, wv, bv);
    attn_kernel<<<dim3(HW / QT, NB), 128>>>();
    out_kernel<<<dim3(HW / 128, NB), 128>>>(x, wo, bo, out);
}